// round 2
// baseline (speedup 1.0000x reference)
#include <cuda_runtime.h>
#include <math.h>

#define NB 4
#define FH 480
#define FW 640
#define NPIX (FH*FW)
#define NSEM 16
#define C_OBS 20
#define VR 100
#define HZ 80
#define MC 480
#define NCELL (VR*VR)          // 10000
#define G0_PER_B (NCELL*HZ)    // 800000
#define AG_Z0 13
#define AG_NZ 12
#define GS_PER_B (NCELL*AG_NZ) // 120000

// Output layout: fp_map_pred (NB*NCELL) | map_pred (NB*20*480*480) | poses (12) | poses (12)
#define OUT_MAP_OFF ((size_t)NB*NCELL)
#define OUT_POSE_OFF (OUT_MAP_OFF + (size_t)NB*C_OBS*MC*MC)

// ---------- scratch (static device globals; no allocation allowed) ----------
__device__ __align__(16) float g_g0[NB*G0_PER_B];          // channel-0 voxels, [b][(x*100+y)*80+z]
__device__ __align__(16) float g_gs[NB*GS_PER_B*16];       // sem voxels, [b][(x*100+y)*12+(z-13)][16]
__device__ float g_pm0[NB*NCELL];                          // clip(agent0)   [b][y*100+x]
__device__ float g_pe0[NB*NCELL];                          // clip(all0)
__device__ float g_ps[NB*NSEM*NCELL];                      // clip(agent_sem/5) [b][c][y*100+x]
__device__ float g_params[NB*8];                           // cos,sin,dx,dy, bi0,bi1,bj0,bj1
__device__ float g_fcal;

// ---------- zero voxel scratch + focal constant ----------
__global__ void zero_kernel() {
    int t = blockIdx.x*blockDim.x + threadIdx.x;
    if (t == 0) {
        g_fcal = (float)(320.0 / tan(39.5 * 3.14159265358979323846 / 180.0));
    }
    float4 z = make_float4(0.f,0.f,0.f,0.f);
    const int n0 = NB*G0_PER_B/4;       // 800000
    const int n1 = NB*GS_PER_B*16/4;    // 1920000
    if (t < n0) ((float4*)g_g0)[t] = z;
    if (t < n1) ((float4*)g_gs)[t] = z;
}

// ---------- trilinear splat ----------
__global__ void splat_kernel(const float* __restrict__ obs, const float* __restrict__ sh) {
    int t = blockIdx.x*blockDim.x + threadIdx.x;
    if (t >= NB*NPIX) return;
    int b   = t / NPIX;
    int pix = t - b*NPIX;
    int i   = pix / FW;
    int j   = pix - i*FW;

    const float* obs_b = obs + (size_t)b*C_OBS*NPIX;
    float depth = __ldg(&obs_b[3*NPIX + pix]);

    float fc = g_fcal;
    float X = ((float)j - 319.5f) * depth / fc;
    float Z = (239.5f - (float)i) * depth / fc;

    float xn = ((X + 250.0f)/5.0f - 50.0f)/100.0f*2.0f;
    float yn = (depth/5.0f - 50.0f)/100.0f*2.0f;
    float zn = ((Z + 88.0f)/5.0f - 32.0f)/80.0f*2.0f;
    xn = fminf(fmaxf(xn, -1.0f), 1.0f);
    yn = fminf(fmaxf(yn, -1.0f), 1.0f);
    zn = fminf(fmaxf(zn, -1.0f), 1.0f);

    float posx = xn*50.0f + 50.0f;
    float posy = yn*50.0f + 50.0f;
    float posz = zn*40.0f + 40.0f;

    float fx = floorf(posx), fy = floorf(posy), fz = floorf(posz);
    float wx[2], wy[2], wz[2];
    int   px_[2], py_[2], pz_[2];
    #pragma unroll
    for (int k = 0; k < 2; k++) {
        float p;
        p = fx + (float)k; { bool s = (p > 0.0f && p < 100.0f); wx[k] = s ? (1.0f - fabsf(posx - p)) : 0.0f; px_[k] = (int)p; }
        p = fy + (float)k; { bool s = (p > 0.0f && p < 100.0f); wy[k] = s ? (1.0f - fabsf(posy - p)) : 0.0f; py_[k] = (int)p; }
        p = fz + (float)k; { bool s = (p > 0.0f && p <  80.0f); wz[k] = s ? (1.0f - fabsf(posz - p)) : 0.0f; pz_[k] = (int)p; }
    }
    // early-out BEFORE touching sh / sem channels
    if ((wx[0]==0.0f && wx[1]==0.0f) || (wy[0]==0.0f && wy[1]==0.0f) || (wz[0]==0.0f && wz[1]==0.0f))
        return;

    float4 s4 = __ldg(&((const float4*)sh)[(size_t)b*NPIX + pix]);
    float sfac = 1.0f + (s4.x + s4.y + s4.z + s4.w) * 0.25f;

    float* g0b = g_g0 + (size_t)b*G0_PER_B;
    float* gsb = g_gs + (size_t)b*GS_PER_B*16;

    float semv[16];
    bool semLoaded = false;

    #pragma unroll
    for (int kx = 0; kx < 2; kx++) {
        if (wx[kx] == 0.0f) continue;
        #pragma unroll
        for (int ky = 0; ky < 2; ky++) {
            float wxy = wx[kx]*wy[ky];
            if (wxy == 0.0f) continue;
            int cellxy = px_[kx]*100 + py_[ky];
            #pragma unroll
            for (int kz = 0; kz < 2; kz++) {
                float w = wxy*wz[kz];
                if (w == 0.0f) continue;
                int pz = pz_[kz];
                atomicAdd(&g0b[cellxy*80 + pz], sfac*w);
                if (pz >= AG_Z0 && pz < AG_Z0 + AG_NZ) {
                    if (!semLoaded) {
                        #pragma unroll
                        for (int c = 0; c < 16; c++)
                            semv[c] = __ldg(&obs_b[(4+c)*NPIX + pix]) * sfac;
                        semLoaded = true;
                    }
                    float* dst = gsb + ((size_t)cellxy*AG_NZ + (pz - AG_Z0))*16;
                    atomicAdd((float4*)(dst+ 0), make_float4(semv[ 0]*w, semv[ 1]*w, semv[ 2]*w, semv[ 3]*w));
                    atomicAdd((float4*)(dst+ 4), make_float4(semv[ 4]*w, semv[ 5]*w, semv[ 6]*w, semv[ 7]*w));
                    atomicAdd((float4*)(dst+ 8), make_float4(semv[ 8]*w, semv[ 9]*w, semv[10]*w, semv[11]*w));
                    atomicAdd((float4*)(dst+12), make_float4(semv[12]*w, semv[13]*w, semv[14]*w, semv[15]*w));
                }
            }
        }
    }
}

// ---------- round + z-projection + clip : 4 threads per cell, cxy-ordered ----------
__global__ void proj_kernel(float* __restrict__ dout) {
    int t = blockIdx.x*blockDim.x + threadIdx.x;
    if (t >= NB*NCELL*4) return;
    int q = t & 3;
    int cellIdx = t >> 2;
    int b   = cellIdx / NCELL;
    int cxy = cellIdx - b*NCELL;         // grid layout index (x*100+y)
    int x = cxy / 100, y = cxy - x*100;
    int cell = y*100 + x;                // output layout index

    // g0: thread q covers z in [q*20, q*20+20) -> contiguous across the 4-thread group
    const float4* g0p = (const float4*)(g_g0 + (size_t)b*G0_PER_B + (size_t)cxy*80) + q*5;
    float a_all = 0.0f, a_ag = 0.0f;
    #pragma unroll
    for (int k = 0; k < 5; k++) {
        float4 v = g0p[k];
        int z = q*20 + k*4;
        float r0 = rintf(v.x), r1 = rintf(v.y), r2 = rintf(v.z), r3 = rintf(v.w);
        a_all += r0 + r1 + r2 + r3;
        a_ag += (z+0 >= 13 && z+0 < 25) ? r0 : 0.0f;
        a_ag += (z+1 >= 13 && z+1 < 25) ? r1 : 0.0f;
        a_ag += (z+2 >= 13 && z+2 < 25) ? r2 : 0.0f;
        a_ag += (z+3 >= 13 && z+3 < 25) ? r3 : 0.0f;
    }

    // sems: thread q owns channels [q*4, q*4+4) = float4 index q of each z slice
    const float4* gsp = (const float4*)(g_gs + ((size_t)b*GS_PER_B + (size_t)cxy*AG_NZ)*16) + q;
    float4 acc = make_float4(0.f,0.f,0.f,0.f);
    #pragma unroll
    for (int zz = 0; zz < AG_NZ; zz++) {
        float4 v = gsp[zz*4];
        acc.x += rintf(v.x);
        acc.y += rintf(v.y);
        acc.z += rintf(v.z);
        acc.w += rintf(v.w);
    }

    // reduce the scalar accumulators across the 4-thread group
    a_all += __shfl_xor_sync(0xFFFFFFFFu, a_all, 1);
    a_all += __shfl_xor_sync(0xFFFFFFFFu, a_all, 2);
    a_ag  += __shfl_xor_sync(0xFFFFFFFFu, a_ag, 1);
    a_ag  += __shfl_xor_sync(0xFFFFFFFFu, a_ag, 2);

    float* psb = g_ps + (size_t)b*NSEM*NCELL;
    psb[(q*4+0)*NCELL + cell] = fminf(fmaxf(acc.x / 5.0f, 0.0f), 1.0f);
    psb[(q*4+1)*NCELL + cell] = fminf(fmaxf(acc.y / 5.0f, 0.0f), 1.0f);
    psb[(q*4+2)*NCELL + cell] = fminf(fmaxf(acc.z / 5.0f, 0.0f), 1.0f);
    psb[(q*4+3)*NCELL + cell] = fminf(fmaxf(acc.w / 5.0f, 0.0f), 1.0f);

    if (q == 0) {
        float pm = fminf(fmaxf(a_ag, 0.0f), 1.0f);
        float pe = fminf(fmaxf(a_all, 0.0f), 1.0f);
        g_pm0[b*NCELL + cell] = pm;
        g_pe0[b*NCELL + cell] = pe;
        dout[(size_t)b*NCELL + cell] = pm;
    }
}

// ---------- pose update + sampling params + conservative active bbox ----------
__global__ void pose_kernel(const float* __restrict__ pose_obs,
                            const float* __restrict__ poses_last,
                            float* __restrict__ dout) {
    int b = threadIdx.x;
    if (b >= NB) return;
    const float DEGf = (float)57.29577951308232;
    float pl0 = poses_last[b*3+0], pl1 = poses_last[b*3+1], pl2 = poses_last[b*3+2];
    float po0 = pose_obs[b*3+0],  po1 = pose_obs[b*3+1],  po2 = pose_obs[b*3+2];
    float t0 = pl2 / DEGf;
    float s0 = sinf(t0), c0 = cosf(t0);
    float y_new = pl1 + po0*s0 + po1*c0;
    float x_new = pl0 + po0*c0 - po1*s0;
    float t_new = pl2 + po2*DEGf;
    t_new = fmodf(t_new - 180.0f, 360.0f) + 180.0f;
    t_new = fmodf(t_new + 180.0f, 360.0f) - 180.0f;

    dout[OUT_POSE_OFF      + b*3+0] = x_new;
    dout[OUT_POSE_OFF      + b*3+1] = y_new;
    dout[OUT_POSE_OFF      + b*3+2] = t_new;
    dout[OUT_POSE_OFF + 12 + b*3+0] = x_new;
    dout[OUT_POSE_OFF + 12 + b*3+1] = y_new;
    dout[OUT_POSE_OFF + 12 + b*3+2] = t_new;

    float stx = -(x_new*100.0f/5.0f - 240.0f)/240.0f;
    float sty = -(y_new*100.0f/5.0f - 240.0f)/240.0f;
    float stt = (90.0f - t_new) * (float)0.017453292519943295;
    float ct = cosf(stt), st = sinf(stt);
    float dx = stx * 239.5f;
    float dy = sty * 239.5f;
    g_params[b*8+0] = ct;
    g_params[b*8+1] = st;
    g_params[b*8+2] = dx;
    g_params[b*8+3] = dy;

    // Conservative bbox of output pixels whose samples can touch the active
    // window (rot sample xr in (189,290), yr in (239,340)).
    float u0 = 189.0f/239.5f - 1.0f, u1 = 290.0f/239.5f - 1.0f;
    float v0 = 239.0f/239.5f - 1.0f, v1 = 340.0f/239.5f - 1.0f;
    // (gx,gy) = R^T (u,v):  gx = ct*u + st*v,  gy = -st*u + ct*v
    float gxmin = 1e9f, gxmax = -1e9f, gymin = 1e9f, gymax = -1e9f;
    #pragma unroll
    for (int k = 0; k < 4; k++) {
        float u = (k & 1) ? u1 : u0;
        float v = (k & 2) ? v1 : v0;
        float gx = ct*u + st*v;
        float gy = -st*u + ct*v;
        gxmin = fminf(gxmin, gx); gxmax = fmaxf(gxmax, gx);
        gymin = fminf(gymin, gy); gymax = fmaxf(gymax, gy);
    }
    float txmin = (gxmin + 1.0f)*239.5f, txmax = (gxmax + 1.0f)*239.5f;
    float tymin = (gymin + 1.0f)*239.5f, tymax = (gymax + 1.0f)*239.5f;
    g_params[b*8+4] = floorf(tymin - dy - 3.0f);   // bi0
    g_params[b*8+5] = ceilf (tymax - dy + 3.0f);   // bi1
    g_params[b*8+6] = floorf(txmin - dx - 3.0f);   // bj0
    g_params[b*8+7] = ceilf (txmax - dx + 3.0f);   // bj1
}

// ---------- fused rotate + translate grid_sample + max : 4 pixels per thread ----------
__device__ __forceinline__ int gather_taps(int b, int i, int j,
                                           float ct, float st, float dx, float dy,
                                           int* lidx, float* lw) {
    float xs = (float)j + dx, ys = (float)i + dy;
    float x0f = floorf(xs), y0f = floorf(ys);
    float wxb = xs - x0f, wxa = 1.0f - wxb;
    float wyb = ys - y0f, wya = 1.0f - wyb;
    float tw[4] = { wxa*wya, wxb*wya, wxa*wyb, wxb*wyb };
    int ix0 = (int)x0f, iy0 = (int)y0f;
    int nt = 0;
    #pragma unroll
    for (int k = 0; k < 4; k++) {
        int tx = ix0 + (k & 1), ty = iy0 + (k >> 1);
        if (tx < 0 || tx >= MC || ty < 0 || ty >= MC) continue;
        float gxr = -1.0f + (float)tx * (2.0f/479.0f);
        float gyr = -1.0f + (float)ty * (2.0f/479.0f);
        float xr = ((ct*gxr - st*gyr) + 1.0f) * 239.5f;
        float yr = ((st*gxr + ct*gyr) + 1.0f) * 239.5f;
        float rx0f = floorf(xr), ry0f = floorf(yr);
        float rb = xr - rx0f, ra = 1.0f - rb;
        float rd = yr - ry0f, rc = 1.0f - rd;
        float rw[4] = { ra*rc, rb*rc, ra*rd, rb*rd };
        int rx0 = (int)rx0f, ry0 = (int)ry0f;
        float twk = tw[k];
        #pragma unroll
        for (int s = 0; s < 4; s++) {
            int ix = rx0 + (s & 1), iy = ry0 + (s >> 1);
            if (ix >= 190 && ix < 290 && iy >= 240 && iy < 340) {
                lidx[nt] = (iy - 240)*100 + (ix - 190);
                lw[nt]   = twk * rw[s];
                nt++;
            }
        }
    }
    return nt;
}

__global__ void map_kernel(const float* __restrict__ maps_last, float* __restrict__ dout) {
    int t = blockIdx.x*blockDim.x + threadIdx.x;
    if (t >= NB*MC*MC/4) return;
    int b   = t / (MC*MC/4);
    int rem = t - b*(MC*MC/4);
    int i  = rem / (MC/4);
    int j4 = (rem - i*(MC/4)) * 4;

    float ct = g_params[b*8+0], st = g_params[b*8+1];
    float dx = g_params[b*8+2], dy = g_params[b*8+3];
    float bi0 = g_params[b*8+4], bi1 = g_params[b*8+5];
    float bj0 = g_params[b*8+6], bj1 = g_params[b*8+7];

    size_t base = (size_t)b*C_OBS*MC*MC + (size_t)i*MC + j4;
    const float4* mlp  = (const float4*)(maps_last + base);
    float4*       outp = (float4*)(dout + OUT_MAP_OFF + base);

    bool inBox = ((float)i >= bi0) && ((float)i <= bi1) &&
                 ((float)(j4+3) >= bj0) && ((float)j4 <= bj1);

    if (!inBox) {
        #pragma unroll
        for (int c = 0; c < C_OBS; c++) {
            float4 v = mlp[c*(MC*MC/4)];
            v.x = fmaxf(v.x, 0.0f); v.y = fmaxf(v.y, 0.0f);
            v.z = fmaxf(v.z, 0.0f); v.w = fmaxf(v.w, 0.0f);
            outp[c*(MC*MC/4)] = v;
        }
        return;
    }

    // slow path: per-pixel taps
    int   nts[4];
    int   lidx[4][16];
    float lw[4][16];
    int total = 0;
    #pragma unroll
    for (int p = 0; p < 4; p++) {
        nts[p] = gather_taps(b, i, j4+p, ct, st, dx, dy, lidx[p], lw[p]);
        total += nts[p];
    }
    if (total == 0) {
        #pragma unroll
        for (int c = 0; c < C_OBS; c++) {
            float4 v = mlp[c*(MC*MC/4)];
            v.x = fmaxf(v.x, 0.0f); v.y = fmaxf(v.y, 0.0f);
            v.z = fmaxf(v.z, 0.0f); v.w = fmaxf(v.w, 0.0f);
            outp[c*(MC*MC/4)] = v;
        }
        return;
    }

    #pragma unroll
    for (int c = 0; c < C_OBS; c++) {
        float4 v = mlp[c*(MC*MC/4)];
        float tv[4] = {0.f, 0.f, 0.f, 0.f};
        if (c != 2 && c != 3) {
            const float* src;
            if      (c == 0) src = g_pm0 + (size_t)b*NCELL;
            else if (c == 1) src = g_pe0 + (size_t)b*NCELL;
            else             src = g_ps  + ((size_t)b*NSEM + (c-4))*NCELL;
            #pragma unroll
            for (int p = 0; p < 4; p++)
                for (int k = 0; k < nts[p]; k++)
                    tv[p] += lw[p][k] * src[lidx[p][k]];
        }
        v.x = fmaxf(v.x, tv[0]); v.y = fmaxf(v.y, tv[1]);
        v.z = fmaxf(v.z, tv[2]); v.w = fmaxf(v.w, tv[3]);
        outp[c*(MC*MC/4)] = v;
    }
}

extern "C" void kernel_launch(void* const* d_in, const int* in_sizes, int n_in,
                              void* d_out, int out_size) {
    const float* obs        = (const float*)d_in[0];
    const float* pose_obs   = (const float*)d_in[1];
    const float* maps_last  = (const float*)d_in[2];
    const float* poses_last = (const float*)d_in[3];
    const float* sh         = (const float*)d_in[4];
    float* out = (float*)d_out;

    zero_kernel<<<(NB*GS_PER_B*16/4 + 255)/256, 256>>>();
    pose_kernel<<<1, 32>>>(pose_obs, poses_last, out);
    splat_kernel<<<NB*NPIX/256, 256>>>(obs, sh);
    proj_kernel<<<(NB*NCELL*4 + 255)/256, 256>>>(out);
    map_kernel<<<(NB*MC*MC/4 + 255)/256, 256>>>(maps_last, out);
}

// round 3
// speedup vs baseline: 1.5041x; 1.5041x over previous
#include <cuda_runtime.h>
#include <math.h>

#define NB 4
#define FH 480
#define FW 640
#define NPIX (FH*FW)
#define NSEM 16
#define C_OBS 20
#define VR 100
#define HZ 80
#define MC 480
#define NCELL (VR*VR)          // 10000
#define G0_PER_B (NCELL*HZ)    // 800000
#define AG_Z0 13
#define AG_NZ 12
#define GS_PER_B (NCELL*AG_NZ) // 120000
#define WIN 160                // window kernel tile (covers worst-case bbox ~149)

// Output layout: fp_map_pred (NB*NCELL) | map_pred (NB*20*480*480) | poses (12) | poses (12)
#define OUT_MAP_OFF ((size_t)NB*NCELL)
#define OUT_POSE_OFF (OUT_MAP_OFF + (size_t)NB*C_OBS*MC*MC)

// ---------- scratch (static device globals; no allocation allowed) ----------
__device__ __align__(16) float g_g0[NB*G0_PER_B];          // ch-0 voxels, [b][(x*100+y)*80+z]
__device__ __align__(16) float g_gs[NB*GS_PER_B*16];       // sem voxels, [b][(x*100+y)*12+(z-13)][16]
__device__ float g_pm0[NB*NCELL];                          // clip(agent0)   [b][y*100+x]
__device__ float g_pe0[NB*NCELL];                          // clip(all0)
__device__ float g_ps[NB*NSEM*NCELL];                      // clip(agent_sem/5) [b][c][y*100+x]
__device__ float g_params[NB*8];                           // cos,sin,dx,dy, bi0,bi1,bj0,bj1
__device__ float g_fcal;

// ---------- zero voxel scratch + focal constant ----------
__global__ void zero_kernel() {
    int t = blockIdx.x*blockDim.x + threadIdx.x;
    if (t == 0) {
        g_fcal = (float)(320.0 / tan(39.5 * 3.14159265358979323846 / 180.0));
    }
    float4 z = make_float4(0.f,0.f,0.f,0.f);
    const int n0 = NB*G0_PER_B/4;       // 800000
    const int n1 = NB*GS_PER_B*16/4;    // 1920000
    if (t < n0) ((float4*)g_g0)[t] = z;
    if (t < n1) ((float4*)g_gs)[t] = z;
}

// ---------- trilinear splat ----------
__global__ void splat_kernel(const float* __restrict__ obs, const float* __restrict__ sh) {
    int t = blockIdx.x*blockDim.x + threadIdx.x;
    if (t >= NB*NPIX) return;
    int b   = t / NPIX;
    int pix = t - b*NPIX;
    int i   = pix / FW;
    int j   = pix - i*FW;

    const float* obs_b = obs + (size_t)b*C_OBS*NPIX;
    // issue both streaming loads up-front for MLP
    float depth = __ldg(&obs_b[3*NPIX + pix]);
    float4 s4   = __ldg(&((const float4*)sh)[(size_t)b*NPIX + pix]);

    float fc = g_fcal;
    float X = ((float)j - 319.5f) * depth / fc;
    float Z = (239.5f - (float)i) * depth / fc;

    float xn = ((X + 250.0f)/5.0f - 50.0f)/100.0f*2.0f;
    float yn = (depth/5.0f - 50.0f)/100.0f*2.0f;
    float zn = ((Z + 88.0f)/5.0f - 32.0f)/80.0f*2.0f;
    xn = fminf(fmaxf(xn, -1.0f), 1.0f);
    yn = fminf(fmaxf(yn, -1.0f), 1.0f);
    zn = fminf(fmaxf(zn, -1.0f), 1.0f);

    float posx = xn*50.0f + 50.0f;
    float posy = yn*50.0f + 50.0f;
    float posz = zn*40.0f + 40.0f;

    float fx = floorf(posx), fy = floorf(posy), fz = floorf(posz);
    float wx[2], wy[2], wz[2];
    int   px_[2], py_[2], pz_[2];
    #pragma unroll
    for (int k = 0; k < 2; k++) {
        float p;
        p = fx + (float)k; { bool s = (p > 0.0f && p < 100.0f); wx[k] = s ? (1.0f - fabsf(posx - p)) : 0.0f; px_[k] = (int)p; }
        p = fy + (float)k; { bool s = (p > 0.0f && p < 100.0f); wy[k] = s ? (1.0f - fabsf(posy - p)) : 0.0f; py_[k] = (int)p; }
        p = fz + (float)k; { bool s = (p > 0.0f && p <  80.0f); wz[k] = s ? (1.0f - fabsf(posz - p)) : 0.0f; pz_[k] = (int)p; }
    }
    if ((wx[0]==0.0f && wx[1]==0.0f) || (wy[0]==0.0f && wy[1]==0.0f) || (wz[0]==0.0f && wz[1]==0.0f))
        return;

    float sfac = 1.0f + (s4.x + s4.y + s4.z + s4.w) * 0.25f;

    float* g0b = g_g0 + (size_t)b*G0_PER_B;
    float* gsb = g_gs + (size_t)b*GS_PER_B*16;

    float semv[16];
    bool semLoaded = false;

    // can the two z-taps be fused into one float2 RED? (aligned & both live)
    bool zpair = (wz[0] != 0.0f) && (wz[1] != 0.0f) && ((pz_[0] & 1) == 0);

    #pragma unroll
    for (int kx = 0; kx < 2; kx++) {
        if (wx[kx] == 0.0f) continue;
        #pragma unroll
        for (int ky = 0; ky < 2; ky++) {
            float wxy = wx[kx]*wy[ky];
            if (wxy == 0.0f) continue;
            int cellxy = px_[kx]*100 + py_[ky];

            // ---- channel 0 ----
            if (zpair) {
                float2 v2 = make_float2(sfac*wxy*wz[0], sfac*wxy*wz[1]);
                atomicAdd((float2*)&g0b[cellxy*80 + pz_[0]], v2);
            } else {
                if (wz[0] != 0.0f) atomicAdd(&g0b[cellxy*80 + pz_[0]], sfac*wxy*wz[0]);
                if (wz[1] != 0.0f) atomicAdd(&g0b[cellxy*80 + pz_[1]], sfac*wxy*wz[1]);
            }

            // ---- sem channels (agent z-band only) ----
            #pragma unroll
            for (int kz = 0; kz < 2; kz++) {
                float w = wxy*wz[kz];
                if (w == 0.0f) continue;
                int pz = pz_[kz];
                if (pz >= AG_Z0 && pz < AG_Z0 + AG_NZ) {
                    if (!semLoaded) {
                        #pragma unroll
                        for (int c = 0; c < 16; c++)
                            semv[c] = __ldg(&obs_b[(4+c)*NPIX + pix]) * sfac;
                        semLoaded = true;
                    }
                    float* dst = gsb + ((size_t)cellxy*AG_NZ + (pz - AG_Z0))*16;
                    atomicAdd((float4*)(dst+ 0), make_float4(semv[ 0]*w, semv[ 1]*w, semv[ 2]*w, semv[ 3]*w));
                    atomicAdd((float4*)(dst+ 4), make_float4(semv[ 4]*w, semv[ 5]*w, semv[ 6]*w, semv[ 7]*w));
                    atomicAdd((float4*)(dst+ 8), make_float4(semv[ 8]*w, semv[ 9]*w, semv[10]*w, semv[11]*w));
                    atomicAdd((float4*)(dst+12), make_float4(semv[12]*w, semv[13]*w, semv[14]*w, semv[15]*w));
                }
            }
        }
    }
}

// ---------- round + z-projection + clip : 4 threads per cell, cxy-ordered ----------
__global__ void proj_kernel(float* __restrict__ dout) {
    int t = blockIdx.x*blockDim.x + threadIdx.x;
    if (t >= NB*NCELL*4) return;
    int q = t & 3;
    int cellIdx = t >> 2;
    int b   = cellIdx / NCELL;
    int cxy = cellIdx - b*NCELL;         // grid layout index (x*100+y)
    int x = cxy / 100, y = cxy - x*100;
    int cell = y*100 + x;                // output layout index

    const float4* g0p = (const float4*)(g_g0 + (size_t)b*G0_PER_B + (size_t)cxy*80) + q*5;
    float a_all = 0.0f, a_ag = 0.0f;
    #pragma unroll
    for (int k = 0; k < 5; k++) {
        float4 v = g0p[k];
        int z = q*20 + k*4;
        float r0 = rintf(v.x), r1 = rintf(v.y), r2 = rintf(v.z), r3 = rintf(v.w);
        a_all += r0 + r1 + r2 + r3;
        a_ag += (z+0 >= 13 && z+0 < 25) ? r0 : 0.0f;
        a_ag += (z+1 >= 13 && z+1 < 25) ? r1 : 0.0f;
        a_ag += (z+2 >= 13 && z+2 < 25) ? r2 : 0.0f;
        a_ag += (z+3 >= 13 && z+3 < 25) ? r3 : 0.0f;
    }

    const float4* gsp = (const float4*)(g_gs + ((size_t)b*GS_PER_B + (size_t)cxy*AG_NZ)*16) + q;
    float4 acc = make_float4(0.f,0.f,0.f,0.f);
    #pragma unroll
    for (int zz = 0; zz < AG_NZ; zz++) {
        float4 v = gsp[zz*4];
        acc.x += rintf(v.x);
        acc.y += rintf(v.y);
        acc.z += rintf(v.z);
        acc.w += rintf(v.w);
    }

    a_all += __shfl_xor_sync(0xFFFFFFFFu, a_all, 1);
    a_all += __shfl_xor_sync(0xFFFFFFFFu, a_all, 2);
    a_ag  += __shfl_xor_sync(0xFFFFFFFFu, a_ag, 1);
    a_ag  += __shfl_xor_sync(0xFFFFFFFFu, a_ag, 2);

    float* psb = g_ps + (size_t)b*NSEM*NCELL;
    psb[(q*4+0)*NCELL + cell] = fminf(fmaxf(acc.x / 5.0f, 0.0f), 1.0f);
    psb[(q*4+1)*NCELL + cell] = fminf(fmaxf(acc.y / 5.0f, 0.0f), 1.0f);
    psb[(q*4+2)*NCELL + cell] = fminf(fmaxf(acc.z / 5.0f, 0.0f), 1.0f);
    psb[(q*4+3)*NCELL + cell] = fminf(fmaxf(acc.w / 5.0f, 0.0f), 1.0f);

    if (q == 0) {
        float pm = fminf(fmaxf(a_ag, 0.0f), 1.0f);
        float pe = fminf(fmaxf(a_all, 0.0f), 1.0f);
        g_pm0[b*NCELL + cell] = pm;
        g_pe0[b*NCELL + cell] = pe;
        dout[(size_t)b*NCELL + cell] = pm;
    }
}

// ---------- pose update + sampling params + conservative active bbox ----------
__global__ void pose_kernel(const float* __restrict__ pose_obs,
                            const float* __restrict__ poses_last,
                            float* __restrict__ dout) {
    int b = threadIdx.x;
    if (b >= NB) return;
    const float DEGf = (float)57.29577951308232;
    float pl0 = poses_last[b*3+0], pl1 = poses_last[b*3+1], pl2 = poses_last[b*3+2];
    float po0 = pose_obs[b*3+0],  po1 = pose_obs[b*3+1],  po2 = pose_obs[b*3+2];
    float t0 = pl2 / DEGf;
    float s0 = sinf(t0), c0 = cosf(t0);
    float y_new = pl1 + po0*s0 + po1*c0;
    float x_new = pl0 + po0*c0 - po1*s0;
    float t_new = pl2 + po2*DEGf;
    t_new = fmodf(t_new - 180.0f, 360.0f) + 180.0f;
    t_new = fmodf(t_new + 180.0f, 360.0f) - 180.0f;

    dout[OUT_POSE_OFF      + b*3+0] = x_new;
    dout[OUT_POSE_OFF      + b*3+1] = y_new;
    dout[OUT_POSE_OFF      + b*3+2] = t_new;
    dout[OUT_POSE_OFF + 12 + b*3+0] = x_new;
    dout[OUT_POSE_OFF + 12 + b*3+1] = y_new;
    dout[OUT_POSE_OFF + 12 + b*3+2] = t_new;

    float stx = -(x_new*100.0f/5.0f - 240.0f)/240.0f;
    float sty = -(y_new*100.0f/5.0f - 240.0f)/240.0f;
    float stt = (90.0f - t_new) * (float)0.017453292519943295;
    float ct = cosf(stt), st = sinf(stt);
    float dx = stx * 239.5f;
    float dy = sty * 239.5f;
    g_params[b*8+0] = ct;
    g_params[b*8+1] = st;
    g_params[b*8+2] = dx;
    g_params[b*8+3] = dy;

    // preimage bbox of the active rot-sample window xr in (189,290), yr in (239,340)
    float u0 = 189.0f/239.5f - 1.0f, u1 = 290.0f/239.5f - 1.0f;
    float v0 = 239.0f/239.5f - 1.0f, v1 = 340.0f/239.5f - 1.0f;
    float gxmin = 1e9f, gxmax = -1e9f, gymin = 1e9f, gymax = -1e9f;
    #pragma unroll
    for (int k = 0; k < 4; k++) {
        float u = (k & 1) ? u1 : u0;
        float v = (k & 2) ? v1 : v0;
        float gx = ct*u + st*v;
        float gy = -st*u + ct*v;
        gxmin = fminf(gxmin, gx); gxmax = fmaxf(gxmax, gx);
        gymin = fminf(gymin, gy); gymax = fmaxf(gymax, gy);
    }
    float txmin = (gxmin + 1.0f)*239.5f, txmax = (gxmax + 1.0f)*239.5f;
    float tymin = (gymin + 1.0f)*239.5f, tymax = (gymax + 1.0f)*239.5f;
    g_params[b*8+4] = floorf(tymin - dy - 3.0f);   // bi0
    g_params[b*8+5] = ceilf (tymax - dy + 3.0f);   // bi1
    g_params[b*8+6] = floorf(txmin - dx - 3.0f);   // bj0
    g_params[b*8+7] = ceilf (txmax - dx + 3.0f);   // bj1
}

// ---------- streaming pass: out = max(maps_last, 0) everywhere ----------
__global__ void map_stream_kernel(const float* __restrict__ maps_last, float* __restrict__ dout) {
    size_t t = (size_t)blockIdx.x*blockDim.x + threadIdx.x;
    const size_t n4 = (size_t)NB*C_OBS*MC*MC/4;
    if (t >= n4) return;
    float4 v = ((const float4*)maps_last)[t];
    v.x = fmaxf(v.x, 0.0f); v.y = fmaxf(v.y, 0.0f);
    v.z = fmaxf(v.z, 0.0f); v.w = fmaxf(v.w, 0.0f);
    ((float4*)(dout + OUT_MAP_OFF))[t] = v;
}

// ---------- window pass: fused rotate+translate grid_sample for bbox pixels ----------
__global__ void map_window_kernel(const float* __restrict__ maps_last, float* __restrict__ dout) {
    int t = blockIdx.x*blockDim.x + threadIdx.x;
    int b   = t / (WIN*WIN);
    int rem = t - b*(WIN*WIN);
    int li = rem / WIN, lj = rem - li*WIN;

    float ct = g_params[b*8+0], st = g_params[b*8+1];
    float dx = g_params[b*8+2], dy = g_params[b*8+3];
    int bi0 = (int)g_params[b*8+4], bi1 = (int)g_params[b*8+5];
    int bj0 = (int)g_params[b*8+6], bj1 = (int)g_params[b*8+7];

    int i = bi0 + li;
    int j = bj0 + lj;
    if (i > bi1 || j > bj1 || i < 0 || i >= MC || j < 0 || j >= MC) return;

    // translation taps
    float xs = (float)j + dx, ys = (float)i + dy;
    float x0f = floorf(xs), y0f = floorf(ys);
    float wxb = xs - x0f, wxa = 1.0f - wxb;
    float wyb = ys - y0f, wya = 1.0f - wyb;
    float tw[4] = { wxa*wya, wxb*wya, wxa*wyb, wxb*wyb };
    int ix0 = (int)x0f, iy0 = (int)y0f;

    int   nt = 0;
    int   lidx[16];
    float lw[16];
    #pragma unroll
    for (int k = 0; k < 4; k++) {
        int tx = ix0 + (k & 1), ty = iy0 + (k >> 1);
        if (tx < 0 || tx >= MC || ty < 0 || ty >= MC) continue;
        float gxr = -1.0f + (float)tx * (2.0f/479.0f);
        float gyr = -1.0f + (float)ty * (2.0f/479.0f);
        float xr = ((ct*gxr - st*gyr) + 1.0f) * 239.5f;
        float yr = ((st*gxr + ct*gyr) + 1.0f) * 239.5f;
        float rx0f = floorf(xr), ry0f = floorf(yr);
        float rb = xr - rx0f, ra = 1.0f - rb;
        float rd = yr - ry0f, rc = 1.0f - rd;
        float rw[4] = { ra*rc, rb*rc, ra*rd, rb*rd };
        int rx0 = (int)rx0f, ry0 = (int)ry0f;
        float twk = tw[k];
        #pragma unroll
        for (int s = 0; s < 4; s++) {
            int ix = rx0 + (s & 1), iy = ry0 + (s >> 1);
            if (ix >= 190 && ix < 290 && iy >= 240 && iy < 340) {
                lidx[nt] = (iy - 240)*100 + (ix - 190);
                lw[nt]   = twk * rw[s];
                nt++;
            }
        }
    }
    if (nt == 0) return;   // stream pass already wrote max(maps_last, 0)

    size_t base = (size_t)b*C_OBS*MC*MC + (size_t)i*MC + j;
    const float* mlp  = maps_last + base;
    float*       outp = dout + OUT_MAP_OFF + base;

    const float* pm = g_pm0 + (size_t)b*NCELL;
    const float* pe = g_pe0 + (size_t)b*NCELL;
    const float* ps = g_ps  + (size_t)b*NSEM*NCELL;

    float tv0 = 0.0f, tv1 = 0.0f;
    for (int k = 0; k < nt; k++) {
        tv0 += lw[k] * pm[lidx[k]];
        tv1 += lw[k] * pe[lidx[k]];
    }
    outp[0]           = fmaxf(mlp[0],           tv0);
    outp[(size_t)MC*MC] = fmaxf(mlp[(size_t)MC*MC], tv1);

    #pragma unroll
    for (int c = 0; c < NSEM; c++) {
        const float* src = ps + (size_t)c*NCELL;
        float tv = 0.0f;
        for (int k = 0; k < nt; k++)
            tv += lw[k] * src[lidx[k]];
        size_t off = (size_t)(c+4)*MC*MC;
        outp[off] = fmaxf(mlp[off], tv);
    }
}

extern "C" void kernel_launch(void* const* d_in, const int* in_sizes, int n_in,
                              void* d_out, int out_size) {
    const float* obs        = (const float*)d_in[0];
    const float* pose_obs   = (const float*)d_in[1];
    const float* maps_last  = (const float*)d_in[2];
    const float* poses_last = (const float*)d_in[3];
    const float* sh         = (const float*)d_in[4];
    float* out = (float*)d_out;

    zero_kernel<<<(NB*GS_PER_B*16/4 + 255)/256, 256>>>();
    pose_kernel<<<1, 32>>>(pose_obs, poses_last, out);
    splat_kernel<<<NB*NPIX/256, 256>>>(obs, sh);
    proj_kernel<<<(NB*NCELL*4 + 255)/256, 256>>>(out);
    map_stream_kernel<<<((NB*C_OBS*MC*MC/4) + 255)/256, 256>>>(maps_last, out);
    map_window_kernel<<<(NB*WIN*WIN + 255)/256, 256>>>(maps_last, out);
}